// round 1
// baseline (speedup 1.0000x reference)
#include <cuda_runtime.h>

#define B_ 4
#define C_ 256
#define N_ 4096

// scratch: normalized-x (Q/K) and conv output (V), both [B][N][C]
__device__ float g_q[(size_t)B_ * N_ * C_];
__device__ float g_v[(size_t)B_ * N_ * C_];

// ---------------------------------------------------------------------------
// Kernel 1: per-pixel channel L2 norm + transpose  x[B,C,N] -> g_q[B,N,C]
// block = (b, 32-pixel tile), 256 threads
// ---------------------------------------------------------------------------
__global__ __launch_bounds__(256) void k_normxpose(const float* __restrict__ x) {
    __shared__ float tile[C_ * 33];   // [c][n] padded
    __shared__ float red[8 * 32];
    __shared__ float rn[32];

    int b  = blockIdx.x >> 7;             // 128 n-tiles per batch
    int n0 = (blockIdx.x & 127) * 32;
    int t  = threadIdx.x;
    int nl = t & 31;
    int cg = t >> 5;                       // 0..7

    const float* xb = x + (size_t)b * C_ * N_;

#pragma unroll 8
    for (int p = 0; p < 32; ++p) {
        int c = cg + p * 8;
        tile[c * 33 + nl] = xb[(size_t)c * N_ + n0 + nl];
    }
    __syncthreads();

    float ss = 0.f;
#pragma unroll 8
    for (int c = cg; c < C_; c += 8) {
        float v = tile[c * 33 + nl];
        ss += v * v;
    }
    red[cg * 32 + nl] = ss;
    __syncthreads();

    if (t < 32) {
        float s = 0.f;
#pragma unroll
        for (int g = 0; g < 8; ++g) s += red[g * 32 + t];
        rn[t] = 1.f / fmaxf(sqrtf(s), 1e-8f);
    }
    __syncthreads();

    float* qb = g_q + (size_t)b * N_ * C_;
#pragma unroll 8
    for (int n = 0; n < 32; ++n) {
        qb[(size_t)(n0 + n) * C_ + t] = tile[t * 33 + n] * rn[n];
    }
}

// ---------------------------------------------------------------------------
// Kernel 2: 1x1 conv  g_v[b][n][o] = sum_c W[o][c] * x[b][c][n] + bias[o]
// block = 64n x 64o tile, 256 threads, 4x4 micro-tile
// ---------------------------------------------------------------------------
__global__ __launch_bounds__(256) void k_conv1x1(const float* __restrict__ x,
                                                 const float* __restrict__ Wm,
                                                 const float* __restrict__ bias) {
    __shared__ float xs[16 * 68];   // [kc][n]
    __shared__ float ws[16 * 68];   // [kc][o]

    int n0 = blockIdx.x * 64;
    int o0 = blockIdx.y * 64;
    int b  = blockIdx.z;
    int t  = threadIdx.x;
    int tx = t & 15, ty = t >> 4;

    const float* xb = x + (size_t)b * C_ * N_;

    float acc[4][4];
#pragma unroll
    for (int r = 0; r < 4; ++r)
#pragma unroll
        for (int c = 0; c < 4; ++c) acc[r][c] = 0.f;

    for (int kc = 0; kc < C_; kc += 16) {
        __syncthreads();
#pragma unroll
        for (int p = 0; p < 4; ++p) {
            int idx = t + p * 256;
            int kk = idx >> 6, nl = idx & 63;
            xs[kk * 68 + nl] = xb[(size_t)(kc + kk) * N_ + n0 + nl];
        }
#pragma unroll
        for (int p = 0; p < 4; ++p) {
            int idx = t + p * 256;
            int ol = idx >> 4, kk = idx & 15;
            ws[kk * 68 + ol] = Wm[(size_t)(o0 + ol) * C_ + kc + kk];
        }
        __syncthreads();

#pragma unroll
        for (int kk = 0; kk < 16; ++kk) {
            float xv[4], wv[4];
#pragma unroll
            for (int r = 0; r < 4; ++r) xv[r] = xs[kk * 68 + ty * 4 + r];
#pragma unroll
            for (int c = 0; c < 4; ++c) wv[c] = ws[kk * 68 + tx * 4 + c];
#pragma unroll
            for (int r = 0; r < 4; ++r)
#pragma unroll
                for (int c = 0; c < 4; ++c) acc[r][c] += xv[r] * wv[c];
        }
    }

    float bv[4];
#pragma unroll
    for (int c = 0; c < 4; ++c) bv[c] = bias[o0 + tx * 4 + c];

    float* vb = g_v + (size_t)b * N_ * C_;
#pragma unroll
    for (int r = 0; r < 4; ++r) {
        float4 o;
        o.x = acc[r][0] + bv[0];
        o.y = acc[r][1] + bv[1];
        o.z = acc[r][2] + bv[2];
        o.w = acc[r][3] + bv[3];
        *reinterpret_cast<float4*>(&vb[(size_t)(n0 + ty * 4 + r) * C_ + o0 + tx * 4]) = o;
    }
}

// ---------------------------------------------------------------------------
// Kernel 3: fused  out[b,c,n] = sum_m relu(q_n . q_m)^2 * v[m][c]
// block = (64-query tile, batch), 256 threads (16x16)
// Q tile resident in smem; loop key tiles: S = Q K^T, P = relu(S)^2, O += P V
// ---------------------------------------------------------------------------
#define QS_STRIDE 260   // 256 + 4 pad
#define KS_STRIDE 68    // 64  + 4 pad   Ks[kk][j]
#define PS_STRIDE 68    // 64  + 4 pad   Ps[i][j]
#define VS_STRIDE 260   // 256 + 4 pad   Vs[mm][c]

__global__ __launch_bounds__(256, 2) void k_ppm_attn(float* __restrict__ out) {
    extern __shared__ float sm[];
    float* Qs = sm;                         // 64 * 260
    float* Ks = Qs + 64 * QS_STRIDE;        // 32 * 68
    float* Ps = Ks + 32 * KS_STRIDE;        // 64 * 68
    float* Vs = Ps + 64 * PS_STRIDE;        // 16 * 260

    int n0 = blockIdx.x * 64;
    int b  = blockIdx.y;
    int t  = threadIdx.x;
    int tx = t & 15, ty = t >> 4;

    const float* qb = g_q + (size_t)b * N_ * C_;
    const float* vb = g_v + (size_t)b * N_ * C_;

    // load Q tile [64 x 256]
#pragma unroll 4
    for (int p = 0; p < 64; ++p) {
        int idx = t + p * 256;
        int row = idx >> 8, col = idx & 255;
        Qs[row * QS_STRIDE + col] = qb[(size_t)(n0 + row) * C_ + col];
    }

    // O accumulators: rows i = ty*4 + r ; cols j = q*64 + tx*4 + cc
    float O[4][4][4];
#pragma unroll
    for (int r = 0; r < 4; ++r)
#pragma unroll
        for (int q = 0; q < 4; ++q)
#pragma unroll
            for (int cc = 0; cc < 4; ++cc) O[r][q][cc] = 0.f;

    for (int mt = 0; mt < N_ / 64; ++mt) {
        int m0 = mt * 64;

        // ---- S = Q K^T  (S[i][j] = sum_c q[n0+i][c] q[m0+j][c]) ----
        float S[4][4];
#pragma unroll
        for (int r = 0; r < 4; ++r)
#pragma unroll
            for (int c = 0; c < 4; ++c) S[r][c] = 0.f;

        for (int kc = 0; kc < C_; kc += 32) {
            __syncthreads();   // previous Ks readers done
#pragma unroll
            for (int p = 0; p < 8; ++p) {
                int idx = t + p * 256;
                int j = idx >> 5, kkl = idx & 31;
                Ks[kkl * KS_STRIDE + j] = qb[(size_t)(m0 + j) * C_ + kc + kkl];
            }
            __syncthreads();

#pragma unroll
            for (int kk = 0; kk < 32; ++kk) {
                float4 kvec = *reinterpret_cast<const float4*>(&Ks[kk * KS_STRIDE + tx * 4]);
                float qv[4];
#pragma unroll
                for (int r = 0; r < 4; ++r) qv[r] = Qs[(ty * 4 + r) * QS_STRIDE + kc + kk];
#pragma unroll
                for (int r = 0; r < 4; ++r) {
                    S[r][0] += qv[r] * kvec.x;
                    S[r][1] += qv[r] * kvec.y;
                    S[r][2] += qv[r] * kvec.z;
                    S[r][3] += qv[r] * kvec.w;
                }
            }
        }
        __syncthreads();

        // ---- P = relu(S)^2 into smem ----
#pragma unroll
        for (int r = 0; r < 4; ++r)
#pragma unroll
            for (int c = 0; c < 4; ++c) {
                float s = S[r][c];
                s = (s > 0.f) ? s * s : 0.f;
                Ps[(ty * 4 + r) * PS_STRIDE + tx * 4 + c] = s;
            }

        // ---- O += P V, streaming V in 16-row chunks ----
        for (int mc = 0; mc < 4; ++mc) {
            __syncthreads();   // previous Vs readers done; Ps writes visible after next sync
#pragma unroll
            for (int p = 0; p < 16; ++p) {
                int idx = t + p * 256;
                int row = idx >> 8, col = idx & 255;
                Vs[row * VS_STRIDE + col] = vb[(size_t)(m0 + mc * 16 + row) * C_ + col];
            }
            __syncthreads();

#pragma unroll
            for (int mm = 0; mm < 16; ++mm) {
                float pv[4];
#pragma unroll
                for (int r = 0; r < 4; ++r)
                    pv[r] = Ps[(ty * 4 + r) * PS_STRIDE + mc * 16 + mm];
                float4 vq[4];
#pragma unroll
                for (int q = 0; q < 4; ++q)
                    vq[q] = *reinterpret_cast<const float4*>(&Vs[mm * VS_STRIDE + q * 64 + tx * 4]);
#pragma unroll
                for (int r = 0; r < 4; ++r)
#pragma unroll
                    for (int q = 0; q < 4; ++q) {
                        O[r][q][0] += pv[r] * vq[q].x;
                        O[r][q][1] += pv[r] * vq[q].y;
                        O[r][q][2] += pv[r] * vq[q].z;
                        O[r][q][3] += pv[r] * vq[q].w;
                    }
            }
        }
    }

    __syncthreads();
    // transpose O through smem (reuse Qs buffer: 256 x 65 = 16640 floats)
    float* Os = Qs;
#pragma unroll
    for (int r = 0; r < 4; ++r)
#pragma unroll
        for (int q = 0; q < 4; ++q)
#pragma unroll
            for (int cc = 0; cc < 4; ++cc) {
                int i = ty * 4 + r;
                int j = q * 64 + tx * 4 + cc;
                Os[j * 65 + i] = O[r][q][cc];
            }
    __syncthreads();

    float* ob = out + (size_t)b * C_ * N_;
    int nl = t & 63, j0 = t >> 6;
#pragma unroll
    for (int j = j0; j < C_; j += 4) {
        ob[(size_t)j * N_ + n0 + nl] = Os[j * 65 + nl];
    }
}

// ---------------------------------------------------------------------------
extern "C" void kernel_launch(void* const* d_in, const int* in_sizes, int n_in,
                              void* d_out, int out_size) {
    const float* x    = (const float*)d_in[0];
    const float* Wm   = (const float*)d_in[1];
    const float* bias = (const float*)d_in[2];
    float* out = (float*)d_out;

    k_normxpose<<<B_ * (N_ / 32), 256>>>(x);
    k_conv1x1<<<dim3(N_ / 64, C_ / 64, B_), 256>>>(x, Wm, bias);

    size_t smem = (size_t)(64 * QS_STRIDE + 32 * KS_STRIDE + 64 * PS_STRIDE + 16 * VS_STRIDE) * sizeof(float);
    cudaFuncSetAttribute(k_ppm_attn, cudaFuncAttributeMaxDynamicSharedMemorySize, (int)smem);
    k_ppm_attn<<<dim3(N_ / 64, B_), 256, (int)smem>>>(out);
}